// round 2
// baseline (speedup 1.0000x reference)
#include <cuda_runtime.h>
#include <stdint.h>

#define NUM_POSES 200

// Precomputed pose matrices: 12 floats per pose (3 rows x [r0 r1 r2 t])
__device__ float g_M[NUM_POSES * 12];

__global__ void build_pose_matrices(const float* __restrict__ R,
                                    const float* __restrict__ T) {
    int p = blockIdx.x * blockDim.x + threadIdx.x;
    if (p >= NUM_POSES) return;

    float wx = R[p * 3 + 0];
    float wy = R[p * 3 + 1];
    float wz = R[p * 3 + 2];

    float theta2 = wx * wx + wy * wy + wz * wz;
    float theta  = sqrtf(theta2 + 1e-12f);
    float a = sinf(theta) / theta;
    float b = (1.0f - cosf(theta)) / fmaxf(theta2, 1e-12f);

    // rot = I + a*K + b*K^2
    float bxy = b * wx * wy;
    float bxz = b * wx * wz;
    float byz = b * wy * wz;

    float r00 = 1.0f - b * (wy * wy + wz * wz);
    float r01 = -a * wz + bxy;
    float r02 =  a * wy + bxz;
    float r10 =  a * wz + bxy;
    float r11 = 1.0f - b * (wx * wx + wz * wz);
    float r12 = -a * wx + byz;
    float r20 = -a * wy + bxz;
    float r21 =  a * wx + byz;
    float r22 = 1.0f - b * (wx * wx + wy * wy);

    float tx = T[p * 3 + 0];
    float ty = T[p * 3 + 1];
    float tz = T[p * 3 + 2];

    float* m = &g_M[p * 12];
    m[0]  = r00; m[1]  = r01; m[2]  = r02; m[3]  = tx;
    m[4]  = r10; m[5]  = r11; m[6]  = r12; m[7]  = ty;
    m[8]  = r20; m[9]  = r21; m[10] = r22; m[11] = tz;
}

__global__ void __launch_bounds__(256)
apply_pose_kernel(const int* __restrict__ n_idx,
                  const float4* __restrict__ E4,   // [N][4] rows of float4
                  float4* __restrict__ out4,       // [N][4] rows of float4
                  int N) {
    __shared__ float sM[NUM_POSES * 12];

    // Stage the pose table into shared memory (9.6 KB)
    for (int i = threadIdx.x; i < NUM_POSES * 12; i += blockDim.x) {
        sM[i] = g_M[i];
    }
    __syncthreads();

    int i = blockIdx.x * blockDim.x + threadIdx.x;
    if (i >= N) return;

    int p = n_idx[i];
    // Defensive clamp: guarantees no OOB even if index dtype assumption is off.
    p = min(max(p, 0), NUM_POSES - 1);
    const float* m = &sM[p * 12];

    // Load E rows (coalesced 128-bit)
    const float4* e = &E4[(size_t)i * 4];
    float4 e0 = e[0];
    float4 e1 = e[1];
    float4 e2 = e[2];
    float4 e3 = e[3];

    float4* o = &out4[(size_t)i * 4];

    // out row r = m[r*4+0]*e0 + m[r*4+1]*e1 + m[r*4+2]*e2 + m[r*4+3]*e3
    #pragma unroll
    for (int r = 0; r < 3; r++) {
        float c0 = m[r * 4 + 0];
        float c1 = m[r * 4 + 1];
        float c2 = m[r * 4 + 2];
        float c3 = m[r * 4 + 3];
        float4 v;
        v.x = fmaf(c0, e0.x, fmaf(c1, e1.x, fmaf(c2, e2.x, c3 * e3.x)));
        v.y = fmaf(c0, e0.y, fmaf(c1, e1.y, fmaf(c2, e2.y, c3 * e3.y)));
        v.z = fmaf(c0, e0.z, fmaf(c1, e1.z, fmaf(c2, e2.z, c3 * e3.z)));
        v.w = fmaf(c0, e0.w, fmaf(c1, e1.w, fmaf(c2, e2.w, c3 * e3.w)));
        o[r] = v;
    }
    // bottom row of M is [0,0,0,1] -> passthrough
    o[3] = e3;
}

extern "C" void kernel_launch(void* const* d_in, const int* in_sizes, int n_in,
                              void* d_out, int out_size) {
    const int*   n_idx = (const int*)d_in[0];
    const float* E     = (const float*)d_in[1];
    const float* R     = (const float*)d_in[2];
    const float* T     = (const float*)d_in[3];
    float*       out   = (float*)d_out;

    // Unambiguous element count: output is N 4x4 fp32 matrices.
    int N = out_size / 16;

    build_pose_matrices<<<1, 256>>>(R, T);

    int threads = 256;
    int blocks = (N + threads - 1) / threads;
    apply_pose_kernel<<<blocks, threads>>>(n_idx, (const float4*)E,
                                           (float4*)out, N);
}

// round 3
// speedup vs baseline: 1.0428x; 1.0428x over previous
#include <cuda_runtime.h>
#include <stdint.h>

#define NUM_POSES 200

// Precomputed pose matrices: 12 floats per pose (3 rows x [r0 r1 r2 t])
__device__ float g_M[NUM_POSES * 12];

__global__ void build_pose_matrices(const float* __restrict__ R,
                                    const float* __restrict__ T) {
    int p = blockIdx.x * blockDim.x + threadIdx.x;
    if (p >= NUM_POSES) return;

    float wx = R[p * 3 + 0];
    float wy = R[p * 3 + 1];
    float wz = R[p * 3 + 2];

    float theta2 = wx * wx + wy * wy + wz * wz;
    float theta  = sqrtf(theta2 + 1e-12f);
    float a = sinf(theta) / theta;
    float b = (1.0f - cosf(theta)) / fmaxf(theta2, 1e-12f);

    // rot = I + a*K + b*K^2
    float bxy = b * wx * wy;
    float bxz = b * wx * wz;
    float byz = b * wy * wz;

    float r00 = 1.0f - b * (wy * wy + wz * wz);
    float r01 = -a * wz + bxy;
    float r02 =  a * wy + bxz;
    float r10 =  a * wz + bxy;
    float r11 = 1.0f - b * (wx * wx + wz * wz);
    float r12 = -a * wx + byz;
    float r20 = -a * wy + bxz;
    float r21 =  a * wx + byz;
    float r22 = 1.0f - b * (wx * wx + wy * wy);

    float tx = T[p * 3 + 0];
    float ty = T[p * 3 + 1];
    float tz = T[p * 3 + 2];

    float* m = &g_M[p * 12];
    m[0]  = r00; m[1]  = r01; m[2]  = r02; m[3]  = tx;
    m[4]  = r10; m[5]  = r11; m[6]  = r12; m[7]  = ty;
    m[8]  = r20; m[9]  = r21; m[10] = r22; m[11] = tz;
}

__global__ void __launch_bounds__(256)
apply_pose_kernel(const int* __restrict__ n_idx,
                  const float4* __restrict__ E4,   // [N][4] rows of float4
                  float4* __restrict__ out4,       // [N][4] rows of float4
                  int N) {
    __shared__ float sM[NUM_POSES * 12];

    // Stage the pose table into shared memory (9.6 KB)
    for (int i = threadIdx.x; i < NUM_POSES * 12; i += blockDim.x) {
        sM[i] = g_M[i];
    }
    __syncthreads();

    int i = blockIdx.x * blockDim.x + threadIdx.x;
    if (i >= N) return;

    int p = n_idx[i];
    // Defensive clamp: guarantees no OOB even if index dtype assumption is off.
    p = min(max(p, 0), NUM_POSES - 1);
    const float* m = &sM[p * 12];

    // Load E rows (coalesced 128-bit)
    const float4* e = &E4[(size_t)i * 4];
    float4 e0 = e[0];
    float4 e1 = e[1];
    float4 e2 = e[2];
    float4 e3 = e[3];

    float4* o = &out4[(size_t)i * 4];

    // out row r = m[r*4+0]*e0 + m[r*4+1]*e1 + m[r*4+2]*e2 + m[r*4+3]*e3
    #pragma unroll
    for (int r = 0; r < 3; r++) {
        float c0 = m[r * 4 + 0];
        float c1 = m[r * 4 + 1];
        float c2 = m[r * 4 + 2];
        float c3 = m[r * 4 + 3];
        float4 v;
        v.x = fmaf(c0, e0.x, fmaf(c1, e1.x, fmaf(c2, e2.x, c3 * e3.x)));
        v.y = fmaf(c0, e0.y, fmaf(c1, e1.y, fmaf(c2, e2.y, c3 * e3.y)));
        v.z = fmaf(c0, e0.z, fmaf(c1, e1.z, fmaf(c2, e2.z, c3 * e3.z)));
        v.w = fmaf(c0, e0.w, fmaf(c1, e1.w, fmaf(c2, e2.w, c3 * e3.w)));
        o[r] = v;
    }
    // bottom row of M is [0,0,0,1] -> passthrough
    o[3] = e3;
}

extern "C" void kernel_launch(void* const* d_in, const int* in_sizes, int n_in,
                              void* d_out, int out_size) {
    const int*   n_idx = (const int*)d_in[0];
    const float* E     = (const float*)d_in[1];
    const float* R     = (const float*)d_in[2];
    const float* T     = (const float*)d_in[3];
    float*       out   = (float*)d_out;

    // Unambiguous element count: output is N 4x4 fp32 matrices.
    int N = out_size / 16;

    build_pose_matrices<<<1, 256>>>(R, T);

    int threads = 256;
    int blocks = (N + threads - 1) / threads;
    apply_pose_kernel<<<blocks, threads>>>(n_idx, (const float4*)E,
                                           (float4*)out, N);
}